// round 1
// baseline (speedup 1.0000x reference)
#include <cuda_runtime.h>
#include <math.h>

#define NJ 140
#define NV 13059
#define NB 28
#define BATCH 512
#define VPAD 13184        // 103 * 128
#define VT 128
#define BT 16
#define KC 28

// Scratch (device globals; no allocations allowed)
__device__ float g_G[BATCH * NJ * 12];    // folded skinning matrices [b][j][3x4 row-major]
__device__ float g_Wt[NJ * VPAD];         // transposed weights [j][v], zero-padded

// ---------------------------------------------------------------------------
// Kernel 0: transpose weights (13059 x 140) -> (140 x VPAD), pad with zeros
// ---------------------------------------------------------------------------
__global__ void transpose_w_kernel(const float* __restrict__ W) {
    __shared__ float tile[32][33];
    int j0 = blockIdx.x * 32;
    int v0 = blockIdx.y * 32;
    int tx = threadIdx.x, ty = threadIdx.y;   // blockDim (32, 8)
    #pragma unroll
    for (int k = 0; k < 4; k++) {
        int v = v0 + ty + k * 8;
        int j = j0 + tx;
        float val = 0.f;
        if (v < NV && j < NJ) val = W[v * NJ + j];
        tile[ty + k * 8][tx] = val;
    }
    __syncthreads();
    #pragma unroll
    for (int k = 0; k < 4; k++) {
        int j = j0 + ty + k * 8;
        int v = v0 + tx;
        if (j < NJ && v < VPAD) g_Wt[j * VPAD + v] = tile[tx][ty + k * 8];
    }
}

// ---------------------------------------------------------------------------
// Kernel 1: per-batch skeleton. One warp per batch element.
//  - Build local joint transforms A_j = [R_j | off_j * scale_j]  (A_0 = [R_0 | Jt_0])
//  - Serial chain: G_i = G_parent(i) @ A_i (12 lanes cooperate via SMEM)
//  - Emit J_out = t_i * s + trans, and folded skinning matrix
//      G' = [ s*Rot | s*(t - Rot@Jt_j) + trans ]
// ---------------------------------------------------------------------------
__global__ void skeleton_kernel(const float* __restrict__ pose,
                                const float* __restrict__ bone_lengths,
                                const float* __restrict__ cbl,
                                const float* __restrict__ trans,
                                const float* __restrict__ scale,
                                const float* __restrict__ Jt,
                                const int*   __restrict__ parent,
                                const int*   __restrict__ bone_mapper,
                                float* __restrict__ out_J) {
    __shared__ float M[4][NJ * 12];
    __shared__ int par_s[NJ];
    int lane = threadIdx.x & 31;
    int w    = threadIdx.x >> 5;
    int b    = blockIdx.x * 4 + w;

    for (int i = threadIdx.x; i < NJ; i += 128) par_s[i] = parent[i];
    __syncthreads();

    float* Mw = M[w];

    // ---- Phase A: local transforms, lanes parallel over joints ----
    for (int j = lane; j < NJ; j += 32) {
        float z = pose[b * NJ * 3 + j * 3 + 0];
        float y = pose[b * NJ * 3 + j * 3 + 1];
        float x = pose[b * NJ * 3 + j * 3 + 2];
        float cx, sx, cy, sy, cz, sz;
        sincosf(x, &sx, &cx);
        sincosf(y, &sy, &cy);
        sincosf(z, &sz, &cz);
        float r00 = cz * cy, r01 = cz * sy * sx - sz * cx, r02 = cz * sy * cx + sz * sx;
        float r10 = sz * cy, r11 = sz * sy * sx + cz * cx, r12 = sz * sy * cx - cz * sx;
        float r20 = -sy,     r21 = cy * sx,                r22 = cy * cx;
        float t0, t1, t2;
        if (j == 0) {
            t0 = Jt[0]; t1 = Jt[1]; t2 = Jt[2];
        } else {
            int p = par_s[j];
            float ox = Jt[j * 3 + 0] - Jt[p * 3 + 0];
            float oy = Jt[j * 3 + 1] - Jt[p * 3 + 1];
            float oz = Jt[j * 3 + 2] - Jt[p * 3 + 2];
            float sc;
            if (j == 1) {
                sc = cbl[b];
            } else {
                int blid = bone_mapper[j];
                if (blid >= 0) {
                    float bv = bone_lengths[b * NB + blid];
                    sc = 2.f / (1.f + expf(-bv * 0.2f));   // 2*sigmoid(x/5)
                } else {
                    sc = 1.f;
                }
            }
            t0 = ox * sc; t1 = oy * sc; t2 = oz * sc;
        }
        float* d = Mw + j * 12;
        d[0] = r00; d[1] = r01; d[2]  = r02; d[3]  = t0;
        d[4] = r10; d[5] = r11; d[6]  = r12; d[7]  = t1;
        d[8] = r20; d[9] = r21; d[10] = r22; d[11] = t2;
    }
    __syncwarp();

    // ---- Phase B: serial kinematic chain (in-place), 12 lanes per step ----
    int m = lane >> 2, n = lane & 3;
    for (int i = 1; i < NJ; i++) {
        int p = par_s[i];
        float val = 0.f;
        if (lane < 12) {
            float a0 = Mw[p * 12 + m * 4 + 0];
            float a1 = Mw[p * 12 + m * 4 + 1];
            float a2 = Mw[p * 12 + m * 4 + 2];
            float b0 = Mw[i * 12 + 0 + n];
            float b1 = Mw[i * 12 + 4 + n];
            float b2 = Mw[i * 12 + 8 + n];
            val = fmaf(a0, b0, fmaf(a1, b1, a2 * b2));
            if (n == 3) val += Mw[p * 12 + m * 4 + 3];
        }
        __syncwarp();
        if (lane < 12) Mw[i * 12 + lane] = val;
        __syncwarp();
    }

    // ---- Phase C: outputs ----
    float s   = scale[b];
    float trx = trans[b * 3 + 0];
    float try_ = trans[b * 3 + 1];
    float trz = trans[b * 3 + 2];
    for (int j = lane; j < NJ; j += 32) {
        const float* d = Mw + j * 12;
        float r00 = d[0], r01 = d[1], r02 = d[2],  t0 = d[3];
        float r10 = d[4], r11 = d[5], r12 = d[6],  t1 = d[7];
        float r20 = d[8], r21 = d[9], r22 = d[10], t2 = d[11];

        // J_out = global joint position * s + trans
        float* jo = out_J + ((size_t)b * NJ + j) * 3;
        jo[0] = fmaf(t0, s, trx);
        jo[1] = fmaf(t1, s, try_);
        jo[2] = fmaf(t2, s, trz);

        // Folded skinning matrix
        float jtx = Jt[j * 3 + 0], jty = Jt[j * 3 + 1], jtz = Jt[j * 3 + 2];
        float g0 = s * (t0 - (r00 * jtx + r01 * jty + r02 * jtz)) + trx;
        float g1 = s * (t1 - (r10 * jtx + r11 * jty + r12 * jtz)) + try_;
        float g2 = s * (t2 - (r20 * jtx + r21 * jty + r22 * jtz)) + trz;
        float* g = g_G + ((size_t)b * NJ + j) * 12;
        g[0] = s * r00; g[1] = s * r01; g[2]  = s * r02; g[3]  = g0;
        g[4] = s * r10; g[5] = s * r11; g[6]  = s * r12; g[7]  = g1;
        g[8] = s * r20; g[9] = s * r21; g[10] = s * r22; g[11] = g2;
    }
}

// ---------------------------------------------------------------------------
// Kernel 2: skinning. Block = 256 threads, tile = 128 vertices x 16 batches.
// Thread = 4 vertices x 2 batches, 3 accumulators each.
// ---------------------------------------------------------------------------
__global__ void __launch_bounds__(256) skin_kernel(const float* __restrict__ vtemp,
                                                   float* __restrict__ out_V) {
    __shared__ __align__(16) float w_s[KC * VT];         // [j][v]
    __shared__ __align__(16) float g_s[BT * KC * 12];    // [b][j][12]

    int tx  = threadIdx.x;
    int vth = tx & 31;
    int bth = tx >> 5;               // 0..7
    int v0  = blockIdx.x * VT;
    int b0  = blockIdx.y * BT;

    float qx[4], qy[4], qz[4];
    #pragma unroll
    for (int r = 0; r < 4; r++) {
        int v = v0 + vth + 32 * r;
        if (v < NV) {
            qx[r] = vtemp[v * 3 + 0];
            qy[r] = vtemp[v * 3 + 1];
            qz[r] = vtemp[v * 3 + 2];
        } else {
            qx[r] = qy[r] = qz[r] = 0.f;
        }
    }

    float acc[2][4][3];
    #pragma unroll
    for (int s = 0; s < 2; s++)
        #pragma unroll
        for (int r = 0; r < 4; r++)
            acc[s][r][0] = acc[s][r][1] = acc[s][r][2] = 0.f;

    const float4* gsrc = (const float4*)g_G;     // 420 float4 per batch
    float4* gdst = (float4*)g_s;

    for (int k0 = 0; k0 < NJ; k0 += KC) {
        __syncthreads();
        // load weights chunk: KC*VT = 3584 floats
        #pragma unroll
        for (int i = 0; i < (KC * VT) / 256; i++) {
            int idx = tx + i * 256;
            int j = idx >> 7, v = idx & 127;
            w_s[idx] = g_Wt[(k0 + j) * VPAD + v0 + v];
        }
        // load G chunk: BT*KC*3 = 1344 float4
        #pragma unroll
        for (int i = 0; i < 6; i++) {
            int idx = tx + i * 256;
            if (idx < BT * KC * 3) {
                int b = idx / (KC * 3);
                int r = idx - b * (KC * 3);
                gdst[b * (KC * 3) + r] = gsrc[(size_t)(b0 + b) * (NJ * 3) + k0 * 3 + r];
            }
        }
        __syncthreads();

        #pragma unroll 4
        for (int j = 0; j < KC; j++) {
            float wv[4];
            #pragma unroll
            for (int r = 0; r < 4; r++) wv[r] = w_s[j * VT + vth + 32 * r];
            #pragma unroll
            for (int s = 0; s < 2; s++) {
                int bl = bth + 8 * s;
                const float4* gp = (const float4*)&g_s[(bl * KC + j) * 12];
                float4 G0 = gp[0];
                float4 G1 = gp[1];
                float4 G2 = gp[2];
                #pragma unroll
                for (int r = 0; r < 4; r++) {
                    float t0 = fmaf(G0.x, qx[r], fmaf(G0.y, qy[r], fmaf(G0.z, qz[r], G0.w)));
                    float t1 = fmaf(G1.x, qx[r], fmaf(G1.y, qy[r], fmaf(G1.z, qz[r], G1.w)));
                    float t2 = fmaf(G2.x, qx[r], fmaf(G2.y, qy[r], fmaf(G2.z, qz[r], G2.w)));
                    acc[s][r][0] = fmaf(wv[r], t0, acc[s][r][0]);
                    acc[s][r][1] = fmaf(wv[r], t1, acc[s][r][1]);
                    acc[s][r][2] = fmaf(wv[r], t2, acc[s][r][2]);
                }
            }
        }
    }

    #pragma unroll
    for (int s = 0; s < 2; s++) {
        int b = b0 + bth + 8 * s;
        #pragma unroll
        for (int r = 0; r < 4; r++) {
            int v = v0 + vth + 32 * r;
            if (v < NV) {
                float* o = out_V + ((size_t)b * NV + v) * 3;
                o[0] = acc[s][r][0];
                o[1] = acc[s][r][1];
                o[2] = acc[s][r][2];
            }
        }
    }
}

// ---------------------------------------------------------------------------
extern "C" void kernel_launch(void* const* d_in, const int* in_sizes, int n_in,
                              void* d_out, int out_size) {
    const float* pose        = (const float*)d_in[0];
    const float* bone_len    = (const float*)d_in[1];
    const float* cbl         = (const float*)d_in[2];
    const float* trans       = (const float*)d_in[3];
    const float* scale       = (const float*)d_in[4];
    const float* v_template  = (const float*)d_in[5];
    const float* t_pose      = (const float*)d_in[6];
    const float* weights     = (const float*)d_in[7];
    const int*   parent      = (const int*)d_in[8];
    const int*   bone_mapper = (const int*)d_in[9];

    float* out   = (float*)d_out;
    float* out_V = out;                                  // [B, NV, 3]
    float* out_J = out + (size_t)BATCH * NV * 3;         // [B, NJ, 3]

    // Kernel 0: transpose weights
    dim3 tb(32, 8);
    dim3 tg((NJ + 31) / 32, (VPAD + 31) / 32);
    transpose_w_kernel<<<tg, tb>>>(weights);

    // Kernel 1: skeletons (4 batches per block, one warp each)
    skeleton_kernel<<<BATCH / 4, 128>>>(pose, bone_len, cbl, trans, scale,
                                        t_pose, parent, bone_mapper, out_J);

    // Kernel 2: skinning
    dim3 sg((NV + VT - 1) / VT, BATCH / BT);
    skin_kernel<<<sg, 256>>>(v_template, out_V);
}